// round 14
// baseline (speedup 1.0000x reference)
#include <cuda_runtime.h>
#include <stdint.h>

// Canny magnitude — barrier-free warp-streaming architecture.
// lane = column (24 outputs + 4 halo lanes each side per warp strip),
// rows streamed vertically with register rolling windows; horizontal
// neighbor exchange via warp shuffles. No shared memory, no __syncthreads.
// Input (16,3,512,512) f32, output (16,1,512,512) f32.

#define H_IMG 512
#define W_IMG 512
#define PLANE (H_IMG * W_IMG)
#define STRIP_COLS 24
#define BAND_ROWS 64
#define N_STRIPS 22      // 22*24 = 528 >= 512
#define N_BANDS  8       // 8*64 = 512

__device__ __forceinline__ int reflect_idx(int i, int n) {
    if (i < 0) i = -i;
    if (i >= n) i = 2 * n - 2 - i;
    return i;
}

#define GQ0 0.054488684548643f
#define GQ1 0.244201342003233f
#define GQ2 0.402619946896247f

__global__ void __launch_bounds__(32)
canny_stream_kernel(const float* __restrict__ in, float* __restrict__ out) {
    const int lane = threadIdx.x;
    const int scol = blockIdx.x;
    const int band = blockIdx.y;
    const int img  = blockIdx.z;

    const int col = scol * STRIP_COLS + lane - 4;   // this lane's image column
    const int lx  = reflect_idx(col, W_IMG);        // horizontal reflect for gray
    const int y0  = band * BAND_ROWS;

    const float* baseR = in + (size_t)img * 3 * PLANE + lx;
    const float* baseG = baseR + PLANE;
    const float* baseB = baseR + 2 * PLANE;
    float* obase = out + (size_t)img * PLANE + col;

    const bool colIn   = (col >= 0) && (col < W_IMG);
    const bool doStore = (lane >= 4) && (lane <= 27) && colIn;
    const bool atL = (col == 0);
    const bool atR = (col == W_IMG - 1);

    // rolling state (all registers)
    float H0=0.f,H1=0.f,H2=0.f,H3=0.f,H4=0.f;                       // htmp rows
    float B0l=0.f,B0c=0.f,B0r=0.f, B1l=0.f,B1c=0.f,B1r=0.f,
          B2l=0.f,B2c=0.f,B2r=0.f;                                  // blur rows
    float M0l=0.f,M0c=0.f,M0r=0.f, M1l=0.f,M1c=0.f,M1r=0.f,
          M2l=0.f,M2c=0.f,M2r=0.f;                                  // mag rows
    int DyP=0, DxP=0, DyN=0, DxN=0;                                 // dir (delayed)

    #pragma unroll 4
    for (int i = 0; i < BAND_ROWS + 8; i++) {
        const int gy = y0 - 4 + i;
        const int ry = reflect_idx(gy, H_IMG);      // vertical reflect
        const int off = ry * W_IMG;

        // grayscale: 0.1495*r + 0.2935*g + 0.057*b + 0.5
        float g = fmaf(0.1495f, baseR[off],
                  fmaf(0.2935f, baseG[off],
                  fmaf(0.057f,  baseB[off], 0.5f)));

        // horizontal 5-tap gaussian via shuffles
        float gm2 = __shfl_up_sync(0xffffffffu, g, 2);
        float gm1 = __shfl_up_sync(0xffffffffu, g, 1);
        float gp1 = __shfl_down_sync(0xffffffffu, g, 1);
        float gp2 = __shfl_down_sync(0xffffffffu, g, 2);
        float hb = GQ0 * (gm2 + gp2) + GQ1 * (gm1 + gp1) + GQ2 * g;
        H0 = H1; H1 = H2; H2 = H3; H3 = H4; H4 = hb;

        if (i >= 4) {
            // vertical 5-tap gaussian -> blur row br = gy-2
            float bv = GQ0 * (H0 + H4) + GQ1 * (H1 + H3) + GQ2 * H2;
            float bl  = __shfl_up_sync(0xffffffffu, bv, 1);
            float brr = __shfl_down_sync(0xffffffffu, bv, 1);
            // sobel horizontal edge-clamp at image borders
            if (atL) bl  = bv;
            if (atR) brr = bv;
            B0l = B1l; B0c = B1c; B0r = B1r;
            B1l = B2l; B1c = B2c; B1r = B2r;
            B2l = bl;  B2c = bv;  B2r = brr;

            if (i >= 6) {
                const int mr = gy - 3;              // mag row
                // sobel vertical edge-clamp (rows clamp to [0,511])
                float t0l = B0l, t0c = B0c, t0r = B0r;
                float t2l = B2l, t2c = B2c, t2r = B2r;
                if (mr == 0)         { t0l = B1l; t0c = B1c; t0r = B1r; }
                if (mr == H_IMG - 1) { t2l = B1l; t2c = B1c; t2r = B1r; }
                float gx  = (t0r - t0l) + 2.0f * (B1r - B1l) + (t2r - t2l);
                float gyv = (t2l - t0l) + 2.0f * (t2c - t0c) + (t2r - t0r);
                float mag = sqrtf(fmaf(gx, gx, fmaf(gyv, gyv, 1e-6f)));
                // octant -> (dy,dx), arithmetic (matches round(atan2/45) mod 8)
                float ax = fabsf(gx), ay = fabsf(gyv);
                int sx = 1 | (__float_as_int(gx)  >> 31);
                int sy = 1 | (__float_as_int(gyv) >> 31);
                int dy = (ay > 0.4142135623730950f * ax) ? -sy : 0;
                int dx = (ay > 2.4142135623730950f * ax) ? 0 : sx;
                // NMS zero-pad: magnitude outside image = 0
                bool magIn = colIn && (mr >= 0) && (mr < H_IMG);
                mag = magIn ? mag : 0.0f;
                // mag left/right neighbors via shuffles
                float ml  = __shfl_up_sync(0xffffffffu, mag, 1);
                float mrg = __shfl_down_sync(0xffffffffu, mag, 1);
                M0l = M1l; M0c = M1c; M0r = M1r;
                M1l = M2l; M1c = M2c; M1r = M2r;
                M2l = ml;  M2c = mag; M2r = mrg;
                DyP = DyN; DxP = DxN; DyN = dy; DxN = dx;

                if (i >= 8) {
                    // output row orow = gy-4; center = M1c, dir = (DyP,DxP)
                    int dyy = DyP, dxx = DxP;
                    // column-select per row for +d and -d neighbors
                    float c0 = (dxx < 0) ? M0l : ((dxx > 0) ? M0r : M0c);
                    float c1 = (dxx < 0) ? M1l : ((dxx > 0) ? M1r : M1c);
                    float c2 = (dxx < 0) ? M2l : ((dxx > 0) ? M2r : M2c);
                    float o0 = (dxx < 0) ? M0r : ((dxx > 0) ? M0l : M0c);
                    float o1 = (dxx < 0) ? M1r : ((dxx > 0) ? M1l : M1c);
                    float o2 = (dxx < 0) ? M2r : ((dxx > 0) ? M2l : M2c);
                    float np = (dyy < 0) ? c0 : ((dyy > 0) ? c2 : c1);
                    float nn = (dyy < 0) ? o2 : ((dyy > 0) ? o0 : o1);
                    float mc = M1c;
                    float res = (fminf(mc - np, mc - nn) > 0.0f) ? mc : 0.0f;
                    if (doStore) obase[(size_t)(gy - 4) * W_IMG] = res;
                }
            }
        }
    }
}

extern "C" void kernel_launch(void* const* d_in, const int* in_sizes, int n_in,
                              void* d_out, int out_size) {
    const float* in = (const float*)d_in[0];
    float* out = (float*)d_out;
    dim3 grid(N_STRIPS, N_BANDS, 16);   // (22, 8, 16) single-warp blocks
    canny_stream_kernel<<<grid, 32>>>(in, out);
}

// round 15
// speedup vs baseline: 1.0383x; 1.0383x over previous
#include <cuda_runtime.h>
#include <stdint.h>

// Canny magnitude — barrier-free warp-streaming, 8 independent warps/block.
// lane = column (24 outputs + 4 halo lanes/side per warp strip), 32-row bands,
// vertical register rolling windows, horizontal exchange via shuffles.
// No shared memory, no __syncthreads. Input (16,3,512,512) -> (16,1,512,512).

#define H_IMG 512
#define W_IMG 512
#define PLANE (H_IMG * W_IMG)
#define STRIP_COLS 24
#define BAND_ROWS 32
#define N_STRIPS 22                  // 22*24 = 528 >= 512
#define N_BANDS  (H_IMG / BAND_ROWS) // 16
#define TASKS    (N_STRIPS * N_BANDS)// 352 per image
#define WPB 8                        // warps per block
#define NT  (WPB * 32)

__device__ __forceinline__ int reflect_idx(int i, int n) {
    if (i < 0) i = -i;
    if (i >= n) i = 2 * n - 2 - i;
    return i;
}

#define GQ0 0.054488684548643f
#define GQ1 0.244201342003233f
#define GQ2 0.402619946896247f

__global__ void __launch_bounds__(NT, 5)
canny_stream_kernel(const float* __restrict__ in, float* __restrict__ out) {
    const int lane = threadIdx.x & 31;
    const int wid  = threadIdx.x >> 5;
    const int task = blockIdx.x * WPB + wid;       // 0..351
    const int img  = blockIdx.z;

    const int scol = task % N_STRIPS;
    const int band = task / N_STRIPS;

    const int col = scol * STRIP_COLS + lane - 4;   // this lane's image column
    const int lx  = reflect_idx(col, W_IMG);        // horizontal reflect for gray
    const int y0  = band * BAND_ROWS;

    const float* baseR = in + (size_t)img * 3 * PLANE + lx;
    const float* baseG = baseR + PLANE;
    const float* baseB = baseR + 2 * PLANE;
    float* obase = out + (size_t)img * PLANE + col;

    const bool colIn   = (col >= 0) && (col < W_IMG);
    const bool doStore = (lane >= 4) && (lane <= 27) && colIn;
    const bool atL = (col == 0);
    const bool atR = (col == W_IMG - 1);

    // rolling state (all registers)
    float H0=0.f,H1=0.f,H2=0.f,H3=0.f,H4=0.f;                       // htmp rows
    float B0l=0.f,B0c=0.f,B0r=0.f, B1l=0.f,B1c=0.f,B1r=0.f,
          B2l=0.f,B2c=0.f,B2r=0.f;                                  // blur rows
    float M0l=0.f,M0c=0.f,M0r=0.f, M1l=0.f,M1c=0.f,M1r=0.f,
          M2l=0.f,M2c=0.f,M2r=0.f;                                  // mag rows
    int DyP=0, DxP=0, DyN=0, DxN=0;                                 // dir (delayed)

    #pragma unroll 4
    for (int i = 0; i < BAND_ROWS + 8; i++) {
        const int gy = y0 - 4 + i;
        const int ry = reflect_idx(gy, H_IMG);      // vertical reflect
        const int off = ry * W_IMG;

        // grayscale: 0.1495*r + 0.2935*g + 0.057*b + 0.5
        float g = fmaf(0.1495f, baseR[off],
                  fmaf(0.2935f, baseG[off],
                  fmaf(0.057f,  baseB[off], 0.5f)));

        // horizontal 5-tap gaussian via shuffles
        float gm2 = __shfl_up_sync(0xffffffffu, g, 2);
        float gm1 = __shfl_up_sync(0xffffffffu, g, 1);
        float gp1 = __shfl_down_sync(0xffffffffu, g, 1);
        float gp2 = __shfl_down_sync(0xffffffffu, g, 2);
        float hb = GQ0 * (gm2 + gp2) + GQ1 * (gm1 + gp1) + GQ2 * g;
        H0 = H1; H1 = H2; H2 = H3; H3 = H4; H4 = hb;

        if (i >= 4) {
            // vertical 5-tap gaussian -> blur row br = gy-2
            float bv = GQ0 * (H0 + H4) + GQ1 * (H1 + H3) + GQ2 * H2;
            float bl  = __shfl_up_sync(0xffffffffu, bv, 1);
            float brr = __shfl_down_sync(0xffffffffu, bv, 1);
            // sobel horizontal edge-clamp at image borders
            if (atL) bl  = bv;
            if (atR) brr = bv;
            B0l = B1l; B0c = B1c; B0r = B1r;
            B1l = B2l; B1c = B2c; B1r = B2r;
            B2l = bl;  B2c = bv;  B2r = brr;

            if (i >= 6) {
                const int mr = gy - 3;              // mag row
                // sobel vertical edge-clamp (rows clamp to [0,511])
                float t0l = B0l, t0c = B0c, t0r = B0r;
                float t2l = B2l, t2c = B2c, t2r = B2r;
                if (mr == 0)         { t0l = B1l; t0c = B1c; t0r = B1r; }
                if (mr == H_IMG - 1) { t2l = B1l; t2c = B1c; t2r = B1r; }
                float gx  = (t0r - t0l) + 2.0f * (B1r - B1l) + (t2r - t2l);
                float gyv = (t2l - t0l) + 2.0f * (t2c - t0c) + (t2r - t0r);
                float mag = sqrtf(fmaf(gx, gx, fmaf(gyv, gyv, 1e-6f)));
                // octant -> (dy,dx), arithmetic (matches round(atan2/45) mod 8)
                float ax = fabsf(gx), ay = fabsf(gyv);
                int sx = 1 | (__float_as_int(gx)  >> 31);
                int sy = 1 | (__float_as_int(gyv) >> 31);
                int dy = (ay > 0.4142135623730950f * ax) ? -sy : 0;
                int dx = (ay > 2.4142135623730950f * ax) ? 0 : sx;
                // NMS zero-pad: magnitude outside image = 0
                bool magIn = colIn && (mr >= 0) && (mr < H_IMG);
                mag = magIn ? mag : 0.0f;
                // mag left/right neighbors via shuffles
                float ml  = __shfl_up_sync(0xffffffffu, mag, 1);
                float mrg = __shfl_down_sync(0xffffffffu, mag, 1);
                M0l = M1l; M0c = M1c; M0r = M1r;
                M1l = M2l; M1c = M2c; M1r = M2r;
                M2l = ml;  M2c = mag; M2r = mrg;
                DyP = DyN; DxP = DxN; DyN = dy; DxN = dx;

                if (i >= 8) {
                    // output row = gy-4; center = M1c, dir = (DyP,DxP)
                    int dyy = DyP, dxx = DxP;
                    float c0 = (dxx < 0) ? M0l : ((dxx > 0) ? M0r : M0c);
                    float c1 = (dxx < 0) ? M1l : ((dxx > 0) ? M1r : M1c);
                    float c2 = (dxx < 0) ? M2l : ((dxx > 0) ? M2r : M2c);
                    float o0 = (dxx < 0) ? M0r : ((dxx > 0) ? M0l : M0c);
                    float o1 = (dxx < 0) ? M1r : ((dxx > 0) ? M1l : M1c);
                    float o2 = (dxx < 0) ? M2r : ((dxx > 0) ? M2l : M2c);
                    float np = (dyy < 0) ? c0 : ((dyy > 0) ? c2 : c1);
                    float nn = (dyy < 0) ? o2 : ((dyy > 0) ? o0 : o1);
                    float mc = M1c;
                    float res = (fminf(mc - np, mc - nn) > 0.0f) ? mc : 0.0f;
                    if (doStore) obase[(size_t)(gy - 4) * W_IMG] = res;
                }
            }
        }
    }
}

extern "C" void kernel_launch(void* const* d_in, const int* in_sizes, int n_in,
                              void* d_out, int out_size) {
    const float* in = (const float*)d_in[0];
    float* out = (float*)d_out;
    dim3 grid(TASKS / WPB, 1, 16);   // (44, 1, 16), 8 warps/block
    canny_stream_kernel<<<grid, NT>>>(in, out);
}

// round 16
// speedup vs baseline: 1.1641x; 1.1212x over previous
#include <cuda_runtime.h>
#include <stdint.h>

// Canny magnitude, fully fused, float4, smem-aliased (22.6KB), 512 threads
// on a 64x32 tile (short phase tails, 100% warp slots).
// gray -> 5x5 separable gaussian (reflect) -> sobel (edge clamp) -> magnitude
// -> arithmetic octant -> 8-dir NMS (zero pad) -> mag * is_max
// Input (16,3,512,512) f32, output (16,1,512,512) f32.

#define H_IMG 512
#define W_IMG 512
#define PLANE (H_IMG * W_IMG)
#define TX 64
#define TY 32
#define NT 512

#define GW 72   // gray stride (halo 4) = 18 float4
#define GH 40
#define HW 68   // h-blur stride (halo 2) = 17 float4
#define BH 36   // blur rows
#define BW 68   // blur stride (valid cols 0..67; P4 over-reads feed masked lanes)
#define MH 34
#define MW 68   // mag stride (valid cols 0..65; 66,67 pad = 0)

#define SA_F 2880               // gray 40*72; blur 36*68=2448 fits
#define MAG_F (MH * MW)         // 2312 floats
#define SB_F (MAG_F + 578)      // + 578 dir words

__device__ __forceinline__ int reflect_idx(int i, int n) {
    if (i < 0) i = -i;
    if (i >= n) i = 2 * n - 2 - i;
    return i;
}

// NMS linear offset in mag tile (stride 68), arithmetic (no LUT).
__device__ __forceinline__ int nms_dir(float gx, float gy) {
    float ax = fabsf(gx), ay = fabsf(gy);
    int sx = 1 | (__float_as_int(gx) >> 31);
    int sy = 1 | (__float_as_int(gy) >> 31);
    int dy = (ay > 0.4142135623730950f * ax) ? -sy : 0;
    int dx = (ay > 2.4142135623730950f * ax) ? 0 : sx;
    return dx + 68 * dy;
}

#define GQ0 0.054488684548643f
#define GQ1 0.244201342003233f
#define GQ2 0.402619946896247f

__global__ void __launch_bounds__(NT, 4)
canny_fused_kernel(const float* __restrict__ in, float* __restrict__ out) {
    __shared__ __align__(16) float sA[SA_F];   // gray -> blur
    __shared__ __align__(16) float sB[SB_F];   // htmp -> mag + dir words

    float*    sBlur = sA;
    float*    sMag  = sB;
    uint32_t* sDw   = (uint32_t*)(sB + MAG_F);
    int8_t*   sDb   = (int8_t*)(sB + MAG_F);

    const int tid = threadIdx.x;
    const int x0  = blockIdx.x * TX;
    const int y0  = blockIdx.y * TY;
    const int b   = blockIdx.z;

    const float* base = in + (size_t)b * 3 * PLANE;

    const bool interior = (x0 >= 4) && (x0 + TX + 4 <= W_IMG) &&
                          (y0 >= 4) && (y0 + TY + 4 <= H_IMG);

    // ---- Phase 1: grayscale into sA (720 f4 items) ----
    if (interior) {
        const float* p = base + (y0 - 4) * W_IMG + (x0 - 4);  // 16B aligned
        #pragma unroll
        for (int it = 0; it < 2; it++) {
            int i = tid + it * NT;
            if (i < GH * 18) {
                int r = i / 18, c4 = (i - r * 18) * 4;
                const float* q = p + r * W_IMG + c4;
                float4 R = *(const float4*)q;
                float4 G = *(const float4*)(q + PLANE);
                float4 B = *(const float4*)(q + 2 * PLANE);
                float4 o;
                o.x = fmaf(0.1495f, R.x, fmaf(0.2935f, G.x, fmaf(0.057f, B.x, 0.5f)));
                o.y = fmaf(0.1495f, R.y, fmaf(0.2935f, G.y, fmaf(0.057f, B.y, 0.5f)));
                o.z = fmaf(0.1495f, R.z, fmaf(0.2935f, G.z, fmaf(0.057f, B.z, 0.5f)));
                o.w = fmaf(0.1495f, R.w, fmaf(0.2935f, G.w, fmaf(0.057f, B.w, 0.5f)));
                *(float4*)(sA + r * GW + c4) = o;
            }
        }
    } else {
        #pragma unroll 1
        for (int i = tid; i < GH * 18; i += NT) {
            int r = i / 18, c4 = (i - r * 18) * 4;
            int yy = reflect_idx(y0 - 4 + r, H_IMG) * W_IMG;
            float o[4];
            #pragma unroll
            for (int j = 0; j < 4; j++) {
                int off = yy + reflect_idx(x0 - 4 + c4 + j, W_IMG);
                o[j] = fmaf(0.1495f, base[off],
                       fmaf(0.2935f, base[off + PLANE],
                       fmaf(0.057f,  base[off + 2 * PLANE], 0.5f)));
            }
            *(float4*)(sA + r * GW + c4) = make_float4(o[0], o[1], o[2], o[3]);
        }
    }
    __syncthreads();

    // ---- Phase 2: horizontal blur sA(gray) -> sB(htmp), 680 items ----
    #pragma unroll
    for (int it = 0; it < 2; it++) {
        int i = tid + it * NT;
        if (i < GH * 17) {
            int r = i / 17, c4 = (i - r * 17) * 4;
            const float* g = sA + r * GW + c4;
            float4 a = *(const float4*)g;
            float4 c = *(const float4*)(g + 4);
            float4 o;
            o.x = GQ0 * (a.x + c.x) + GQ1 * (a.y + a.w) + GQ2 * a.z;
            o.y = GQ0 * (a.y + c.y) + GQ1 * (a.z + c.x) + GQ2 * a.w;
            o.z = GQ0 * (a.z + c.z) + GQ1 * (a.w + c.y) + GQ2 * c.x;
            o.w = GQ0 * (a.w + c.w) + GQ1 * (c.x + c.z) + GQ2 * c.y;
            *(float4*)(sB + r * HW + c4) = o;
        }
    }
    __syncthreads();

    // ---- Phase 3: vertical blur sB(htmp) -> sA(blur), 612 items ----
    #pragma unroll
    for (int it = 0; it < 2; it++) {
        int i = tid + it * NT;
        if (i < BH * 17) {
            int r = i / 17, c4 = (i - r * 17) * 4;
            const float* h = sB + r * HW + c4;
            float4 v0 = *(const float4*)h;
            float4 v1 = *(const float4*)(h + HW);
            float4 v2 = *(const float4*)(h + 2 * HW);
            float4 v3 = *(const float4*)(h + 3 * HW);
            float4 v4 = *(const float4*)(h + 4 * HW);
            float4 o;
            o.x = GQ0 * (v0.x + v4.x) + GQ1 * (v1.x + v3.x) + GQ2 * v2.x;
            o.y = GQ0 * (v0.y + v4.y) + GQ1 * (v1.y + v3.y) + GQ2 * v2.y;
            o.z = GQ0 * (v0.z + v4.z) + GQ1 * (v1.z + v3.z) + GQ2 * v2.z;
            o.w = GQ0 * (v0.w + v4.w) + GQ1 * (v1.w + v3.w) + GQ2 * v2.w;
            *(float4*)(sBlur + r * BW + c4) = o;
        }
    }
    __syncthreads();

    // ---- Phase 4: sobel (column-sum factored) + dir -> sB, 578 items ----
    if (interior) {
        #pragma unroll
        for (int it = 0; it < 2; it++) {
            int i = tid + it * NT;
            if (i < MH * 17) {
                int r = i / 17, c0 = (i - r * 17) * 4;
                const float* bp = sBlur + r * BW + c0;
                float t0[8], t1[8], t2[8];
                *(float4*)t0       = *(const float4*)bp;
                *(float4*)(t0 + 4) = *(const float4*)(bp + 4);
                *(float4*)t1       = *(const float4*)(bp + BW);
                *(float4*)(t1 + 4) = *(const float4*)(bp + BW + 4);
                *(float4*)t2       = *(const float4*)(bp + 2 * BW);
                *(float4*)(t2 + 4) = *(const float4*)(bp + 2 * BW + 4);
                // column sums: A = t0 + 2*t1 + t2 (for gx), C = t2 - t0 (for gy)
                float A[8], C[8];
                #pragma unroll
                for (int j = 0; j < 8; j++) {
                    A[j] = t0[j] + 2.0f * t1[j] + t2[j];
                    C[j] = t2[j] - t0[j];
                }
                float m[4];
                uint32_t dpack = 0;
                #pragma unroll
                for (int j = 0; j < 4; j++) {
                    float gx = A[j + 2] - A[j];
                    float gy = C[j] + 2.0f * C[j + 1] + C[j + 2];
                    float mm = sqrtf(fmaf(gx, gx, fmaf(gy, gy, 1e-6f)));
                    int d = nms_dir(gx, gy);
                    if (c0 + j > 65) { mm = 0.0f; d = 1; }
                    m[j] = mm;
                    dpack |= ((uint32_t)(uint8_t)(int8_t)d) << (8 * j);
                }
                *(float4*)(sMag + r * MW + c0) = make_float4(m[0], m[1], m[2], m[3]);
                sDw[(r * MW + c0) >> 2] = dpack;
            }
        }
    } else {
        #pragma unroll 1
        for (int i = tid; i < MH * MW; i += NT) {
            int r = i / MW, c = i - r * MW;
            float mm = 0.0f;
            int8_t dch = 1;
            if (c <= 65) {
                int my = y0 - 1 + r;
                int mx = x0 - 1 + c;
                if (my >= 0 && my < H_IMG && mx >= 0 && mx < W_IMG) {
                    int iy0 = max(my - 1, 0)         - (y0 - 2);
                    int iy1 = r + 1;
                    int iy2 = min(my + 1, H_IMG - 1) - (y0 - 2);
                    int ix0 = max(mx - 1, 0)         - (x0 - 2);
                    int ix1 = c + 1;
                    int ix2 = min(mx + 1, W_IMG - 1) - (x0 - 2);
                    float b00 = sBlur[iy0*BW+ix0], b01 = sBlur[iy0*BW+ix1], b02 = sBlur[iy0*BW+ix2];
                    float b10 = sBlur[iy1*BW+ix0],                          b12 = sBlur[iy1*BW+ix2];
                    float b20 = sBlur[iy2*BW+ix0], b21 = sBlur[iy2*BW+ix1], b22 = sBlur[iy2*BW+ix2];
                    float gx = (b02 - b00) + 2.0f * (b12 - b10) + (b22 - b20);
                    float gy = (b20 - b00) + 2.0f * (b21 - b01) + (b22 - b02);
                    mm = sqrtf(fmaf(gx, gx, fmaf(gy, gy, 1e-6f)));
                    dch = (int8_t)nms_dir(gx, gy);
                }
            }
            sMag[i] = mm;
            sDb[i] = dch;
        }
    }
    __syncthreads();

    // ---- Phase 5: NMS + write, exactly 1 f4 item/thread ----
    float* obase = out + ((size_t)b * H_IMG + y0) * W_IMG + x0;
    {
        const int r  = tid >> 4;                  // 0..31
        const int c0 = (tid & 15) * 4;
        const int bse = (r + 1) * MW + c0;        // 16B aligned
        float4 m0 = *(const float4*)(sMag + bse);
        float4 m1 = *(const float4*)(sMag + bse + 4);
        uint32_t wlo = sDw[bse >> 2];
        uint32_t whi = sDw[(bse >> 2) + 1];
        uint32_t dv  = __funnelshift_r(wlo, whi, 8);  // dirs for cols c0+1..c0+4
        float ctr[4] = { m0.y, m0.z, m0.w, m1.x };
        float res[4];
        #pragma unroll
        for (int j = 0; j < 4; j++) {
            int d = (int)(int8_t)(dv >> (8 * j));
            int lin = bse + 1 + j;
            float mc = ctr[j];
            float sp = mc - sMag[lin + d];
            float sn = mc - sMag[lin - d];
            res[j] = (fminf(sp, sn) > 0.0f) ? mc : 0.0f;
        }
        *(float4*)(obase + r * W_IMG + c0) = make_float4(res[0], res[1], res[2], res[3]);
    }
}

extern "C" void kernel_launch(void* const* d_in, const int* in_sizes, int n_in,
                              void* d_out, int out_size) {
    const float* in = (const float*)d_in[0];
    float* out = (float*)d_out;
    dim3 grid(W_IMG / TX, H_IMG / TY, 16);   // (8, 16, 16)
    canny_fused_kernel<<<grid, NT>>>(in, out);
}